// round 6
// baseline (speedup 1.0000x reference)
#include <cuda_runtime.h>
#include <math.h>

// Problem constants
#define BATCH   128
#define NTOK    196
#define CDIM    768
#define NHEADS  12
#define HD      64
#define MROWS   (BATCH * NTOK)      // 25088
#define NQKV    (3 * CDIM)          // 2304
#define BHTOT   (BATCH * NHEADS)    // 1536
#define BK      16

// Scratch (device globals: allocation-free rule)
__device__ float g_Q[BHTOT * NTOK * HD];
__device__ float g_K[BHTOT * NTOK * HD];
__device__ float g_V[BHTOT * NTOK * HD];
__device__ float g_AO[MROWS * CDIM];
__device__ float g_cos[NTOK * 32];
__device__ float g_sin[NTOK * 32];

typedef unsigned long long u64;

__device__ __forceinline__ u64 pack2(float lo, float hi) {
    u64 r; asm("mov.b64 %0,{%1,%2};" : "=l"(r) : "f"(lo), "f"(hi)); return r;
}
__device__ __forceinline__ void unpack2(u64 v, float &lo, float &hi) {
    asm("mov.b64 {%0,%1},%2;" : "=f"(lo), "=f"(hi) : "l"(v));
}
__device__ __forceinline__ void fma2(u64 &d, u64 a, u64 b) {
    asm("fma.rn.f32x2 %0,%1,%2,%3;" : "=l"(d) : "l"(a), "l"(b), "l"(d));
}

// ---------------------------------------------------------------------------
// RoPE table: cos/sin for (t, d) with d in [0,32)
// ---------------------------------------------------------------------------
__global__ void rope_table_kernel() {
    int idx = blockIdx.x * blockDim.x + threadIdx.x;
    if (idx >= NTOK * 32) return;
    int t = idx / 32, dd = idx % 32;
    int y = t / 14, x = t % 14;
    float pos = (dd < 16) ? (float)y : (float)x;
    int j = (dd < 16) ? dd : dd - 16;
    float invf = exp2f(-(float)j * (log2f(10000.0f) / 16.0f));
    float ang = pos * invf;
    float s, c;
    sincosf(ang, &s, &c);
    g_cos[idx] = c;
    g_sin[idx] = s;
}

// ---------------------------------------------------------------------------
// f32x2 tiled SGEMM (unchanged from passing R4 version)
// ---------------------------------------------------------------------------
__global__ __launch_bounds__(256, 2)
void gemm_f32x2_kernel(const float* __restrict__ A, const float* __restrict__ B,
                       const float* __restrict__ bias, float* __restrict__ Cout,
                       int K, int mode) {
    __shared__ float As[BK][256];   // m-duplicated: As[k][2m]==As[k][2m+1]
    __shared__ float Bs[BK][128];

    int tid = threadIdx.x;
    int bm = blockIdx.y, bn = blockIdx.x;
    int lrow = tid >> 1;
    int lk   = (tid & 1) * 8;

    const float* Aptr = A + ((size_t)(bm * 128 + lrow)) * K + lk;
    const float* Bptr = B + ((size_t)(bn * 128 + lrow)) * K + lk;

    int ty = tid >> 4, tx = tid & 15;

    u64 acc[8][4];
#pragma unroll
    for (int i = 0; i < 8; i++)
#pragma unroll
        for (int j = 0; j < 4; j++) acc[i][j] = 0ull;

    float4 a0 = *(const float4*)(Aptr);
    float4 a1 = *(const float4*)(Aptr + 4);
    float4 b0 = *(const float4*)(Bptr);
    float4 b1 = *(const float4*)(Bptr + 4);

    for (int k0 = 0; k0 < K; k0 += BK) {
        __syncthreads();
        {
            float av[8] = {a0.x, a0.y, a0.z, a0.w, a1.x, a1.y, a1.z, a1.w};
            float bv[8] = {b0.x, b0.y, b0.z, b0.w, b1.x, b1.y, b1.z, b1.w};
#pragma unroll
            for (int q = 0; q < 8; q++) {
                *(u64*)&As[lk + q][2 * lrow] = pack2(av[q], av[q]);
                Bs[lk + q][lrow] = bv[q];
            }
        }
        __syncthreads();
        if (k0 + BK < K) {
            a0 = *(const float4*)(Aptr + k0 + BK);
            a1 = *(const float4*)(Aptr + k0 + BK + 4);
            b0 = *(const float4*)(Bptr + k0 + BK);
            b1 = *(const float4*)(Bptr + k0 + BK + 4);
        }
#pragma unroll
        for (int kk = 0; kk < BK; kk++) {
            u64 aa[8];
#pragma unroll
            for (int ii = 0; ii < 4; ii++) {
                ulonglong2 t2 = *(const ulonglong2*)&As[kk][ty * 16 + ii * 4];
                aa[2 * ii] = t2.x; aa[2 * ii + 1] = t2.y;
            }
            u64 bb[4];
#pragma unroll
            for (int j = 0; j < 4; j++)
                bb[j] = *(const u64*)&Bs[kk][2 * tx + 32 * j];
#pragma unroll
            for (int i = 0; i < 8; i++)
#pragma unroll
                for (int j = 0; j < 4; j++)
                    fma2(acc[i][j], aa[i], bb[j]);
        }
    }

    if (mode == 0) {
#pragma unroll
        for (int i = 0; i < 8; i++) {
            int m = bm * 128 + ty * 8 + i;
            int b = m / NTOK, t = m % NTOK;
#pragma unroll
            for (int jh = 0; jh < 2; jh++) {
                float vA0, vA1, vB0, vB1;
                unpack2(acc[i][2 * jh],     vA0, vA1);
                unpack2(acc[i][2 * jh + 1], vB0, vB1);
                int nlo = bn * 128 + 64 * jh + 2 * tx;
#pragma unroll
                for (int p = 0; p < 2; p++) {
                    int n = nlo + p;
                    float lo = (p ? vA1 : vA0) + bias[n];
                    float hi = (p ? vB1 : vB0) + bias[n + 32];
                    int s = n / CDIM;
                    int r = n % CDIM;
                    int h = r >> 6, d = r & 63;   // d < 32 by construction
                    float* dst = (s == 0) ? g_Q : (s == 1) ? g_K : g_V;
                    size_t off = (((size_t)(b * NHEADS + h)) * NTOK + t) * HD;
                    if (s < 2) {
                        float c  = g_cos[t * 32 + d];
                        float sn = g_sin[t * 32 + d];
                        dst[off + d]      = lo * c - hi * sn;
                        dst[off + d + 32] = hi * c + lo * sn;
                    } else {
                        dst[off + d]      = lo;
                        dst[off + d + 32] = hi;
                    }
                }
            }
        }
    } else {
#pragma unroll
        for (int i = 0; i < 8; i++) {
            int m = bm * 128 + ty * 8 + i;
#pragma unroll
            for (int j = 0; j < 4; j++) {
                int n = bn * 128 + 32 * j + 2 * tx;
                float v0, v1;
                unpack2(acc[i][j], v0, v1);
                float2 w = make_float2(v0 + bias[n], v1 + bias[n + 1]);
                *(float2*)&Cout[(size_t)m * CDIM + n] = w;
            }
        }
    }
}

// ---------------------------------------------------------------------------
// Attention v2: one block per (b,h). FFMA2 + 2 rows per warp pass.
// smem: Kt[64][196] f32, Vs[196][64] f32, Qd[8][2][64] u64 (dup pairs),
//       Pd[8][2][196] u64 (dup pairs).  Total 133,632 B.
// Row pairing: warp handles (rr, rr+98) for rr = warp, warp+8, ... < 98.
// QK: acc pairs over adjacent j (Kt j-contiguous -> LDS.64), Q dup broadcast.
// PV: acc pairs over adjacent d (Vs d-contiguous -> LDS.64), P dup broadcast.
// ---------------------------------------------------------------------------
#define ATT_SMEM_BYTES (64 * NTOK * 4 + NTOK * 64 * 4 + 8 * 2 * 64 * 8 + 8 * 2 * NTOK * 8)

__global__ void attention_kernel(float* __restrict__ AO) {
    extern __shared__ float sm[];
    float* Kt = sm;                               // [64][196]
    float* Vs = Kt + 64 * NTOK;                   // [196][64]
    u64*  Qd  = (u64*)(Vs + NTOK * 64);           // [8][2][64]
    u64*  Pd  = Qd + 8 * 2 * 64;                  // [8][2][196]

    int bh = blockIdx.x;
    int b = bh / NHEADS, h = bh % NHEADS;
    int tid = threadIdx.x, warp = tid >> 5, lane = tid & 31;

    const float* Qg = g_Q + (size_t)bh * NTOK * HD;
    const float* Kg = g_K + (size_t)bh * NTOK * HD;
    const float* Vg = g_V + (size_t)bh * NTOK * HD;

    for (int i = tid; i < NTOK * HD; i += 256) {
        int j = i >> 6, d = i & 63;
        Kt[d * NTOK + j] = Kg[i];
        Vs[i] = Vg[i];
    }
    __syncthreads();

    const float scale = 0.125f;   // 64^-0.5
    u64* Qd0 = Qd + warp * 2 * 64;
    u64* Qd1 = Qd0 + 64;
    u64* Pd0 = Pd + warp * 2 * NTOK;
    u64* Pd1 = Pd0 + NTOK;

    for (int rr = warp; rr < 98; rr += 8) {
        int r0 = rr, r1 = rr + 98;

        // stage Q rows duplicated
        float q00 = Qg[r0 * HD + lane], q01 = Qg[r0 * HD + lane + 32];
        float q10 = Qg[r1 * HD + lane], q11 = Qg[r1 * HD + lane + 32];
        Qd0[lane]      = pack2(q00, q00);
        Qd0[lane + 32] = pack2(q01, q01);
        Qd1[lane]      = pack2(q10, q10);
        Qd1[lane + 32] = pack2(q11, q11);
        __syncwarp();

        // ---- QK^T: lane owns column pairs pr = lane + 32t ----
        u64 acc[4][2];
#pragma unroll
        for (int t = 0; t < 4; t++) { acc[t][0] = 0ull; acc[t][1] = 0ull; }

#pragma unroll 4
        for (int i = 0; i < HD; i++) {
            u64 q0 = Qd0[i];
            u64 q1 = Qd1[i];
#pragma unroll
            for (int t = 0; t < 3; t++) {
                u64 kt = *(const u64*)&Kt[i * NTOK + 2 * (lane + 32 * t)];
                fma2(acc[t][0], q0, kt);
                fma2(acc[t][1], q1, kt);
            }
        }
        if (lane < 2) {   // tail pair pr = lane + 96 (96,97)
            int j0 = 2 * (lane + 96);
#pragma unroll 4
            for (int i = 0; i < HD; i++) {
                u64 kt = *(const u64*)&Kt[i * NTOK + j0];
                fma2(acc[3][0], Qd0[i], kt);
                fma2(acc[3][1], Qd1[i], kt);
            }
        }

        // unpack & scale
        float sA[4][2], sB[4][2];
#pragma unroll
        for (int t = 0; t < 4; t++)
#pragma unroll
            for (int r = 0; r < 2; r++) {
                float lo, hi; unpack2(acc[t][r], lo, hi);
                sA[t][r] = lo * scale; sB[t][r] = hi * scale;
            }

        // row maxes
        float m0 = -1e30f, m1 = -1e30f;
#pragma unroll
        for (int t = 0; t < 3; t++) {
            m0 = fmaxf(m0, fmaxf(sA[t][0], sB[t][0]));
            m1 = fmaxf(m1, fmaxf(sA[t][1], sB[t][1]));
        }
        if (lane < 2) {
            m0 = fmaxf(m0, fmaxf(sA[3][0], sB[3][0]));
            m1 = fmaxf(m1, fmaxf(sA[3][1], sB[3][1]));
        }
#pragma unroll
        for (int o = 16; o; o >>= 1) {
            m0 = fmaxf(m0, __shfl_xor_sync(0xFFFFFFFFu, m0, o));
            m1 = fmaxf(m1, __shfl_xor_sync(0xFFFFFFFFu, m1, o));
        }

        // exp, store duplicated P, accumulate z
        float z0 = 0.0f, z1 = 0.0f;
#pragma unroll
        for (int t = 0; t < 4; t++) {
            int pr = lane + 32 * t;
            if (pr < 98) {
                int j0 = 2 * pr;
                float e0 = __expf(sA[t][0] - m0), e1 = __expf(sB[t][0] - m0);
                Pd0[j0]     = pack2(e0, e0);
                Pd0[j0 + 1] = pack2(e1, e1);
                z0 += e0 + e1;
                float f0 = __expf(sA[t][1] - m1), f1 = __expf(sB[t][1] - m1);
                Pd1[j0]     = pack2(f0, f0);
                Pd1[j0 + 1] = pack2(f1, f1);
                z1 += f0 + f1;
            }
        }
#pragma unroll
        for (int o = 16; o; o >>= 1) {
            z0 += __shfl_xor_sync(0xFFFFFFFFu, z0, o);
            z1 += __shfl_xor_sync(0xFFFFFFFFu, z1, o);
        }
        float inv0 = 1.0f / z0, inv1 = 1.0f / z1;
        __syncwarp();

        // ---- P@V: lane owns d pair (2*lane, 2*lane+1) ----
        u64 o0 = 0ull, o1 = 0ull;
#pragma unroll 4
        for (int j = 0; j < NTOK; j++) {
            u64 v2 = *(const u64*)&Vs[j * HD + 2 * lane];
            fma2(o0, Pd0[j], v2);
            fma2(o1, Pd1[j], v2);
        }
        float x0, y0, x1, y1;
        unpack2(o0, x0, y0);
        unpack2(o1, x1, y1);
        size_t base0 = ((size_t)b * NTOK + r0) * CDIM + h * HD + 2 * lane;
        size_t base1 = ((size_t)b * NTOK + r1) * CDIM + h * HD + 2 * lane;
        *(float2*)&AO[base0] = make_float2(x0 * inv0, y0 * inv0);
        *(float2*)&AO[base1] = make_float2(x1 * inv1, y1 * inv1);
        __syncwarp();
    }
}

// ---------------------------------------------------------------------------
extern "C" void kernel_launch(void* const* d_in, const int* in_sizes, int n_in,
                              void* d_out, int out_size) {
    const float* x      = (const float*)d_in[0];
    const float* qkv_w  = (const float*)d_in[1];
    const float* qkv_b  = (const float*)d_in[2];
    const float* proj_w = (const float*)d_in[3];
    const float* proj_b = (const float*)d_in[4];
    float* out = (float*)d_out;

    // 1. RoPE tables (needed by the QKV epilogue)
    rope_table_kernel<<<(NTOK * 32 + 255) / 256, 256>>>();

    // 2. QKV GEMM + fused RoPE + scatter to [B,H,N,HD]
    {
        dim3 grid(NQKV / 128, MROWS / 128);   // (18, 196)
        gemm_f32x2_kernel<<<grid, 256>>>(x, qkv_w, qkv_b, nullptr, CDIM, 0);
    }

    // 3. Attention
    {
        float* aoptr; cudaGetSymbolAddress((void**)&aoptr, g_AO);
        cudaFuncSetAttribute(attention_kernel,
                             cudaFuncAttributeMaxDynamicSharedMemorySize,
                             ATT_SMEM_BYTES);
        attention_kernel<<<BHTOT, 256, ATT_SMEM_BYTES>>>(aoptr);
    }

    // 4. Output projection
    {
        float* aoptr; cudaGetSymbolAddress((void**)&aoptr, g_AO);
        dim3 grid(CDIM / 128, MROWS / 128);   // (6, 196)
        gemm_f32x2_kernel<<<grid, 256>>>(aoptr, proj_w, proj_b, out, CDIM, 1);
    }
}

// round 13
// speedup vs baseline: 1.9617x; 1.9617x over previous
#include <cuda_runtime.h>
#include <cuda_bf16.h>
#include <math.h>
#include <stdint.h>

// Problem constants
#define BATCH   128
#define NTOK    196
#define CDIM    768
#define NHEADS  12
#define HD      64
#define MROWS   (BATCH * NTOK)      // 25088
#define NQKV    (3 * CDIM)          // 2304
#define BHTOT   (BATCH * NHEADS)    // 1536
#define KDIM    768

typedef unsigned long long u64;
typedef __nv_bfloat16 bf16;

// ---------------------------------------------------------------------------
// Device global scratch (allocation-free rule)
// ---------------------------------------------------------------------------
__device__ float g_Q[BHTOT * NTOK * HD];
__device__ float g_K[BHTOT * NTOK * HD];
__device__ float g_V[BHTOT * NTOK * HD];
__device__ float g_AO[MROWS * CDIM];
__device__ float g_cos[NTOK * 32];
__device__ float g_sin[NTOK * 32];
// bf16 split buffers
__device__ bf16 g_xh[MROWS * CDIM];
__device__ bf16 g_xl[MROWS * CDIM];
__device__ bf16 g_wh[NQKV * CDIM];
__device__ bf16 g_wl[NQKV * CDIM];
__device__ bf16 g_ph[CDIM * CDIM];
__device__ bf16 g_pl[CDIM * CDIM];
__device__ bf16 g_aoh[MROWS * CDIM];
__device__ bf16 g_aol[MROWS * CDIM];

// ---------------------------------------------------------------------------
// helpers
// ---------------------------------------------------------------------------
__device__ __forceinline__ uint32_t smem_u32(const void* p) {
    uint32_t a;
    asm("{ .reg .u64 t; cvta.to.shared.u64 t, %1; cvt.u32.u64 %0, t; }"
        : "=r"(a) : "l"(p));
    return a;
}
__device__ __forceinline__ u64 pack2(float lo, float hi) {
    u64 r; asm("mov.b64 %0,{%1,%2};" : "=l"(r) : "f"(lo), "f"(hi)); return r;
}
__device__ __forceinline__ void unpack2(u64 v, float &lo, float &hi) {
    asm("mov.b64 {%0,%1},%2;" : "=f"(lo), "=f"(hi) : "l"(v));
}
__device__ __forceinline__ void fma2(u64 &d, u64 a, u64 b) {
    asm("fma.rn.f32x2 %0,%1,%2,%3;" : "=l"(d) : "l"(a), "l"(b), "l"(d));
}
__device__ __forceinline__ void ldsm_x4(uint32_t* r, uint32_t addr) {
    asm volatile("ldmatrix.sync.aligned.m8n8.x4.shared.b16 {%0,%1,%2,%3}, [%4];"
                 : "=r"(r[0]), "=r"(r[1]), "=r"(r[2]), "=r"(r[3]) : "r"(addr));
}
__device__ __forceinline__ void mma16816(float* c, const uint32_t* a,
                                         const uint32_t* b) {
    asm volatile(
        "mma.sync.aligned.m16n8k16.row.col.f32.bf16.bf16.f32 "
        "{%0,%1,%2,%3}, {%4,%5,%6,%7}, {%8,%9}, {%0,%1,%2,%3};"
        : "+f"(c[0]), "+f"(c[1]), "+f"(c[2]), "+f"(c[3])
        : "r"(a[0]), "r"(a[1]), "r"(a[2]), "r"(a[3]), "r"(b[0]), "r"(b[1]));
}

// ---------------------------------------------------------------------------
// RoPE table
// ---------------------------------------------------------------------------
__global__ void rope_table_kernel() {
    int idx = blockIdx.x * blockDim.x + threadIdx.x;
    if (idx >= NTOK * 32) return;
    int t = idx / 32, dd = idx % 32;
    int y = t / 14, x = t % 14;
    float pos = (dd < 16) ? (float)y : (float)x;
    int j = (dd < 16) ? dd : dd - 16;
    float invf = exp2f(-(float)j * (log2f(10000.0f) / 16.0f));
    float ang = pos * invf;
    float s, c;
    sincosf(ang, &s, &c);
    g_cos[idx] = c;
    g_sin[idx] = s;
}

// ---------------------------------------------------------------------------
// fp32 -> bf16 (hi, lo) residual split
// ---------------------------------------------------------------------------
__global__ void split_kernel(const float4* __restrict__ src,
                             __nv_bfloat162* __restrict__ hi,
                             __nv_bfloat162* __restrict__ lo, int n4) {
    int i = blockIdx.x * blockDim.x + threadIdx.x;
    if (i >= n4) return;
    float4 v = src[i];
    bf16 h0 = __float2bfloat16(v.x), h1 = __float2bfloat16(v.y);
    bf16 h2 = __float2bfloat16(v.z), h3 = __float2bfloat16(v.w);
    bf16 l0 = __float2bfloat16(v.x - __bfloat162float(h0));
    bf16 l1 = __float2bfloat16(v.y - __bfloat162float(h1));
    bf16 l2 = __float2bfloat16(v.z - __bfloat162float(h2));
    bf16 l3 = __float2bfloat16(v.w - __bfloat162float(h3));
    hi[2 * i]     = __halves2bfloat162(h0, h1);
    hi[2 * i + 1] = __halves2bfloat162(h2, h3);
    lo[2 * i]     = __halves2bfloat162(l0, l1);
    lo[2 * i + 1] = __halves2bfloat162(l2, l3);
}

// ---------------------------------------------------------------------------
// mma.sync bf16 3-split GEMM: C[m,n] = (Ahi+Alo)(Bhi+Blo)^T + bias
// BM=128 BN=128 BK=32, 8 warps (4m x 2n), warp tile 32x64.
// STATIC smem, single stage, plain LDG->STS loads (no cp.async).
// mode 0: fused RoPE + scatter to g_Q/g_K/g_V.  mode 1: Cout + bias.
// ---------------------------------------------------------------------------
#define ROWP 40   // bf16 elems per smem row (32 data + 8 pad), 80 B

__global__ __launch_bounds__(256)
void hmma_gemm_kernel(const bf16* __restrict__ Ahi, const bf16* __restrict__ Alo,
                      const bf16* __restrict__ Bhi, const bf16* __restrict__ Blo,
                      const float* __restrict__ bias, float* __restrict__ Cout,
                      int mode) {
    __shared__ bf16 sAh[128 * ROWP];
    __shared__ bf16 sAl[128 * ROWP];
    __shared__ bf16 sBh[128 * ROWP];
    __shared__ bf16 sBl[128 * ROWP];

    int tid = threadIdx.x, wid = tid >> 5, lane = tid & 31;
    int bn = blockIdx.x, bm = blockIdx.y;
    int wm = wid >> 1, wn = wid & 1;     // 4 x 2 warp grid

    float acc[2][8][4];
#pragma unroll
    for (int i = 0; i < 2; i++)
#pragma unroll
        for (int j = 0; j < 8; j++)
#pragma unroll
            for (int q = 0; q < 4; q++) acc[i][j][q] = 0.0f;

    // load coords: 512 uint4 per array; thread does tid and tid+256
    int r0 = tid >> 2,          c80 = tid & 3;
    int r1 = (tid + 256) >> 2,  c81 = (tid + 256) & 3;

    const int NCH = KDIM / 32;   // 24
    for (int c = 0; c < NCH; c++) {
        size_t a0 = ((size_t)(bm * 128 + r0)) * KDIM + c * 32 + c80 * 8;
        size_t a1 = ((size_t)(bm * 128 + r1)) * KDIM + c * 32 + c81 * 8;
        size_t b0 = ((size_t)(bn * 128 + r0)) * KDIM + c * 32 + c80 * 8;
        size_t b1 = ((size_t)(bn * 128 + r1)) * KDIM + c * 32 + c81 * 8;
        uint4 tAh0 = *(const uint4*)&Ahi[a0];
        uint4 tAh1 = *(const uint4*)&Ahi[a1];
        uint4 tAl0 = *(const uint4*)&Alo[a0];
        uint4 tAl1 = *(const uint4*)&Alo[a1];
        uint4 tBh0 = *(const uint4*)&Bhi[b0];
        uint4 tBh1 = *(const uint4*)&Bhi[b1];
        uint4 tBl0 = *(const uint4*)&Blo[b0];
        uint4 tBl1 = *(const uint4*)&Blo[b1];
        __syncthreads();   // previous chunk's compute is done
        *(uint4*)&sAh[r0 * ROWP + c80 * 8] = tAh0;
        *(uint4*)&sAh[r1 * ROWP + c81 * 8] = tAh1;
        *(uint4*)&sAl[r0 * ROWP + c80 * 8] = tAl0;
        *(uint4*)&sAl[r1 * ROWP + c81 * 8] = tAl1;
        *(uint4*)&sBh[r0 * ROWP + c80 * 8] = tBh0;
        *(uint4*)&sBh[r1 * ROWP + c81 * 8] = tBh1;
        *(uint4*)&sBl[r0 * ROWP + c80 * 8] = tBl0;
        *(uint4*)&sBl[r1 * ROWP + c81 * 8] = tBl1;
        __syncthreads();

        int lr = lane & 7, sel = lane >> 3;
#pragma unroll
        for (int kk = 0; kk < 2; kk++) {
            // A fragments [mi][split][4]
            uint32_t af[2][2][4];
#pragma unroll
            for (int mi = 0; mi < 2; mi++) {
                int m = wm * 32 + mi * 16 + (sel & 1) * 8 + lr;
                int k = kk * 16 + (sel >> 1) * 8;
                ldsm_x4(af[mi][0], smem_u32(&sAh[m * ROWP + k]));
                ldsm_x4(af[mi][1], smem_u32(&sAl[m * ROWP + k]));
            }
            // B fragments [np][split][4]
            uint32_t bfr[4][2][4];
#pragma unroll
            for (int np = 0; np < 4; np++) {
                int n = wn * 64 + np * 16 + (sel >> 1) * 8 + lr;
                int k = kk * 16 + (sel & 1) * 8;
                ldsm_x4(bfr[np][0], smem_u32(&sBh[n * ROWP + k]));
                ldsm_x4(bfr[np][1], smem_u32(&sBl[n * ROWP + k]));
            }
#pragma unroll
            for (int mi = 0; mi < 2; mi++)
#pragma unroll
                for (int nt = 0; nt < 8; nt++) {
                    const uint32_t* bh = &bfr[nt >> 1][0][(nt & 1) * 2];
                    const uint32_t* bl = &bfr[nt >> 1][1][(nt & 1) * 2];
                    mma16816(acc[mi][nt], af[mi][0], bh);
                    mma16816(acc[mi][nt], af[mi][0], bl);
                    mma16816(acc[mi][nt], af[mi][1], bh);
                }
        }
    }

    // ---------------- epilogue (registers -> global) ----------------
    int nbase = bn * 128 + wn * 64;
    if (mode == 0) {
        int s = nbase / CDIM;
        int h = (nbase % CDIM) >> 6;
        float* dst = (s == 0) ? g_Q : (s == 1) ? g_K : g_V;
#pragma unroll
        for (int mi = 0; mi < 2; mi++)
#pragma unroll
            for (int rg = 0; rg < 2; rg++) {
                int m = bm * 128 + wm * 32 + mi * 16 + rg * 8 + (lane >> 2);
                int b = m / NTOK, t = m % NTOK;
                size_t off = (((size_t)(b * NHEADS + h)) * NTOK + t) * HD;
#pragma unroll
                for (int nt = 0; nt < 4; nt++)
#pragma unroll
                    for (int i = 0; i < 2; i++) {
                        int d = nt * 8 + 2 * (lane & 3) + i;
                        float lo = acc[mi][nt][rg * 2 + i]     + bias[nbase + d];
                        float hi = acc[mi][nt + 4][rg * 2 + i] + bias[nbase + d + 32];
                        if (s < 2) {
                            float cc = g_cos[t * 32 + d];
                            float sn = g_sin[t * 32 + d];
                            dst[off + d]      = lo * cc - hi * sn;
                            dst[off + d + 32] = hi * cc + lo * sn;
                        } else {
                            dst[off + d]      = lo;
                            dst[off + d + 32] = hi;
                        }
                    }
            }
    } else {
#pragma unroll
        for (int mi = 0; mi < 2; mi++)
#pragma unroll
            for (int rg = 0; rg < 2; rg++) {
                int m = bm * 128 + wm * 32 + mi * 16 + rg * 8 + (lane >> 2);
#pragma unroll
                for (int nt = 0; nt < 8; nt++) {
                    int n = nbase + nt * 8 + 2 * (lane & 3);
                    float2 w = make_float2(acc[mi][nt][rg * 2]     + bias[n],
                                           acc[mi][nt][rg * 2 + 1] + bias[n + 1]);
                    *(float2*)&Cout[(size_t)m * CDIM + n] = w;
                }
            }
    }
}

// ---------------------------------------------------------------------------
// Attention (unchanged passing version): one block per (b,h), FFMA2, 2 rows/warp
// ---------------------------------------------------------------------------
#define ATT_SMEM_BYTES (64 * NTOK * 4 + NTOK * 64 * 4 + 8 * 2 * 64 * 8 + 8 * 2 * NTOK * 8)

__global__ void attention_kernel(float* __restrict__ AO) {
    extern __shared__ float sm[];
    float* Kt = sm;                               // [64][196]
    float* Vs = Kt + 64 * NTOK;                   // [196][64]
    u64*  Qd  = (u64*)(Vs + NTOK * 64);           // [8][2][64]
    u64*  Pd  = Qd + 8 * 2 * 64;                  // [8][2][196]

    int bh = blockIdx.x;
    int b = bh / NHEADS, h = bh % NHEADS;
    int tid = threadIdx.x, warp = tid >> 5, lane = tid & 31;

    const float* Qg = g_Q + (size_t)bh * NTOK * HD;
    const float* Kg = g_K + (size_t)bh * NTOK * HD;
    const float* Vg = g_V + (size_t)bh * NTOK * HD;

    for (int i = tid; i < NTOK * HD; i += 256) {
        int j = i >> 6, d = i & 63;
        Kt[d * NTOK + j] = Kg[i];
        Vs[i] = Vg[i];
    }
    __syncthreads();

    const float scale = 0.125f;
    u64* Qd0 = Qd + warp * 2 * 64;
    u64* Qd1 = Qd0 + 64;
    u64* Pd0 = Pd + warp * 2 * NTOK;
    u64* Pd1 = Pd0 + NTOK;

    for (int rr = warp; rr < 98; rr += 8) {
        int r0 = rr, r1 = rr + 98;

        float q00 = Qg[r0 * HD + lane], q01 = Qg[r0 * HD + lane + 32];
        float q10 = Qg[r1 * HD + lane], q11 = Qg[r1 * HD + lane + 32];
        Qd0[lane]      = pack2(q00, q00);
        Qd0[lane + 32] = pack2(q01, q01);
        Qd1[lane]      = pack2(q10, q10);
        Qd1[lane + 32] = pack2(q11, q11);
        __syncwarp();

        u64 acc[4][2];
#pragma unroll
        for (int t = 0; t < 4; t++) { acc[t][0] = 0ull; acc[t][1] = 0ull; }

#pragma unroll 4
        for (int i = 0; i < HD; i++) {
            u64 q0 = Qd0[i];
            u64 q1 = Qd1[i];
#pragma unroll
            for (int t = 0; t < 3; t++) {
                u64 kt = *(const u64*)&Kt[i * NTOK + 2 * (lane + 32 * t)];
                fma2(acc[t][0], q0, kt);
                fma2(acc[t][1], q1, kt);
            }
        }
        if (lane < 2) {
            int j0 = 2 * (lane + 96);
#pragma unroll 4
            for (int i = 0; i < HD; i++) {
                u64 kt = *(const u64*)&Kt[i * NTOK + j0];
                fma2(acc[3][0], Qd0[i], kt);
                fma2(acc[3][1], Qd1[i], kt);
            }
        }

        float sA[4][2], sB[4][2];
#pragma unroll
        for (int t = 0; t < 4; t++)
#pragma unroll
            for (int r = 0; r < 2; r++) {
                float lo, hi; unpack2(acc[t][r], lo, hi);
                sA[t][r] = lo * scale; sB[t][r] = hi * scale;
            }

        float m0 = -1e30f, m1 = -1e30f;
#pragma unroll
        for (int t = 0; t < 3; t++) {
            m0 = fmaxf(m0, fmaxf(sA[t][0], sB[t][0]));
            m1 = fmaxf(m1, fmaxf(sA[t][1], sB[t][1]));
        }
        if (lane < 2) {
            m0 = fmaxf(m0, fmaxf(sA[3][0], sB[3][0]));
            m1 = fmaxf(m1, fmaxf(sA[3][1], sB[3][1]));
        }
#pragma unroll
        for (int o = 16; o; o >>= 1) {
            m0 = fmaxf(m0, __shfl_xor_sync(0xFFFFFFFFu, m0, o));
            m1 = fmaxf(m1, __shfl_xor_sync(0xFFFFFFFFu, m1, o));
        }

        float z0 = 0.0f, z1 = 0.0f;
#pragma unroll
        for (int t = 0; t < 4; t++) {
            int pr = lane + 32 * t;
            if (pr < 98) {
                int j0 = 2 * pr;
                float e0 = __expf(sA[t][0] - m0), e1 = __expf(sB[t][0] - m0);
                Pd0[j0]     = pack2(e0, e0);
                Pd0[j0 + 1] = pack2(e1, e1);
                z0 += e0 + e1;
                float f0 = __expf(sA[t][1] - m1), f1 = __expf(sB[t][1] - m1);
                Pd1[j0]     = pack2(f0, f0);
                Pd1[j0 + 1] = pack2(f1, f1);
                z1 += f0 + f1;
            }
        }
#pragma unroll
        for (int o = 16; o; o >>= 1) {
            z0 += __shfl_xor_sync(0xFFFFFFFFu, z0, o);
            z1 += __shfl_xor_sync(0xFFFFFFFFu, z1, o);
        }
        float inv0 = 1.0f / z0, inv1 = 1.0f / z1;
        __syncwarp();

        u64 o0 = 0ull, o1 = 0ull;
#pragma unroll 4
        for (int j = 0; j < NTOK; j++) {
            u64 v2 = *(const u64*)&Vs[j * HD + 2 * lane];
            fma2(o0, Pd0[j], v2);
            fma2(o1, Pd1[j], v2);
        }
        float x0, y0, x1, y1;
        unpack2(o0, x0, y0);
        unpack2(o1, x1, y1);
        size_t base0 = ((size_t)b * NTOK + r0) * CDIM + h * HD + 2 * lane;
        size_t base1 = ((size_t)b * NTOK + r1) * CDIM + h * HD + 2 * lane;
        *(float2*)&AO[base0] = make_float2(x0 * inv0, y0 * inv0);
        *(float2*)&AO[base1] = make_float2(x1 * inv1, y1 * inv1);
        __syncwarp();
    }
}

// ---------------------------------------------------------------------------
extern "C" void kernel_launch(void* const* d_in, const int* in_sizes, int n_in,
                              void* d_out, int out_size) {
    const float* x      = (const float*)d_in[0];
    const float* qkv_w  = (const float*)d_in[1];
    const float* qkv_b  = (const float*)d_in[2];
    const float* proj_w = (const float*)d_in[3];
    const float* proj_b = (const float*)d_in[4];
    float* out = (float*)d_out;

    bf16 *xh, *xl, *wh, *wl, *ph, *pl, *aoh, *aol;
    float *aop;
    cudaGetSymbolAddress((void**)&xh, g_xh);   cudaGetSymbolAddress((void**)&xl, g_xl);
    cudaGetSymbolAddress((void**)&wh, g_wh);   cudaGetSymbolAddress((void**)&wl, g_wl);
    cudaGetSymbolAddress((void**)&ph, g_ph);   cudaGetSymbolAddress((void**)&pl, g_pl);
    cudaGetSymbolAddress((void**)&aoh, g_aoh); cudaGetSymbolAddress((void**)&aol, g_aol);
    cudaGetSymbolAddress((void**)&aop, g_AO);

    // 1. RoPE tables
    rope_table_kernel<<<(NTOK * 32 + 255) / 256, 256>>>();

    // 2. bf16 splits of x, qkv_w, proj_w
    {
        int n4 = MROWS * CDIM / 4;
        split_kernel<<<(n4 + 255) / 256, 256>>>((const float4*)x,
            (__nv_bfloat162*)xh, (__nv_bfloat162*)xl, n4);
        n4 = NQKV * CDIM / 4;
        split_kernel<<<(n4 + 255) / 256, 256>>>((const float4*)qkv_w,
            (__nv_bfloat162*)wh, (__nv_bfloat162*)wl, n4);
        n4 = CDIM * CDIM / 4;
        split_kernel<<<(n4 + 255) / 256, 256>>>((const float4*)proj_w,
            (__nv_bfloat162*)ph, (__nv_bfloat162*)pl, n4);
    }

    // 3. QKV GEMM (mma.sync) + fused RoPE + scatter
    {
        dim3 grid(NQKV / 128, MROWS / 128);   // (18, 196)
        hmma_gemm_kernel<<<grid, 256>>>(xh, xl, wh, wl, qkv_b, nullptr, 0);
    }

    // 4. Attention
    {
        cudaFuncSetAttribute(attention_kernel,
                             cudaFuncAttributeMaxDynamicSharedMemorySize,
                             ATT_SMEM_BYTES);
        attention_kernel<<<BHTOT, 256, ATT_SMEM_BYTES>>>(aop);
    }

    // 5. split AO -> bf16
    {
        int n4 = MROWS * CDIM / 4;
        split_kernel<<<(n4 + 255) / 256, 256>>>((const float4*)aop,
            (__nv_bfloat162*)aoh, (__nv_bfloat162*)aol, n4);
    }

    // 6. Output projection (mma.sync)
    {
        dim3 grid(CDIM / 128, MROWS / 128);   // (6, 196)
        hmma_gemm_kernel<<<grid, 256>>>(aoh, aol, ph, pl, proj_b, out, 1);
    }
}

// round 15
// speedup vs baseline: 2.0000x; 1.0195x over previous
#include <cuda_runtime.h>
#include <cuda_bf16.h>
#include <math.h>
#include <stdint.h>

// Problem constants
#define BATCH   128
#define NTOK    196
#define CDIM    768
#define NHEADS  12
#define HD      64
#define MROWS   (BATCH * NTOK)      // 25088
#define NQKV    (3 * CDIM)          // 2304
#define BHTOT   (BATCH * NHEADS)    // 1536
#define KDIM    768

typedef unsigned long long u64;
typedef __nv_bfloat16 bf16;

// ---------------------------------------------------------------------------
// Device global scratch (allocation-free rule)
// ---------------------------------------------------------------------------
__device__ float g_Q[BHTOT * NTOK * HD];
__device__ float g_K[BHTOT * NTOK * HD];
__device__ float g_V[BHTOT * NTOK * HD];
__device__ float g_AO[MROWS * CDIM];
__device__ float g_cos[NTOK * 32];
__device__ float g_sin[NTOK * 32];
// bf16 split buffers
__device__ bf16 g_xh[MROWS * CDIM];
__device__ bf16 g_xl[MROWS * CDIM];
__device__ bf16 g_wh[NQKV * CDIM];
__device__ bf16 g_wl[NQKV * CDIM];
__device__ bf16 g_ph[CDIM * CDIM];
__device__ bf16 g_pl[CDIM * CDIM];
__device__ bf16 g_aoh[MROWS * CDIM];
__device__ bf16 g_aol[MROWS * CDIM];

// ---------------------------------------------------------------------------
// helpers
// ---------------------------------------------------------------------------
__device__ __forceinline__ uint32_t smem_u32(const void* p) {
    uint32_t a;
    asm("{ .reg .u64 t; cvta.to.shared.u64 t, %1; cvt.u32.u64 %0, t; }"
        : "=r"(a) : "l"(p));
    return a;
}
__device__ __forceinline__ void ldsm_x4(uint32_t* r, uint32_t addr) {
    asm volatile("ldmatrix.sync.aligned.m8n8.x4.shared.b16 {%0,%1,%2,%3}, [%4];"
                 : "=r"(r[0]), "=r"(r[1]), "=r"(r[2]), "=r"(r[3]) : "r"(addr));
}
__device__ __forceinline__ void mma16816(float* c, const uint32_t* a,
                                         const uint32_t* b) {
    asm volatile(
        "mma.sync.aligned.m16n8k16.row.col.f32.bf16.bf16.f32 "
        "{%0,%1,%2,%3}, {%4,%5,%6,%7}, {%8,%9}, {%0,%1,%2,%3};"
        : "+f"(c[0]), "+f"(c[1]), "+f"(c[2]), "+f"(c[3])
        : "r"(a[0]), "r"(a[1]), "r"(a[2]), "r"(a[3]), "r"(b[0]), "r"(b[1]));
}
// pack two f32 -> bf16x2 (v0 -> lower half, v1 -> upper half)
__device__ __forceinline__ uint32_t packbf(float v0, float v1) {
    uint32_t r;
    asm("cvt.rn.bf16x2.f32 %0, %1, %2;" : "=r"(r) : "f"(v1), "f"(v0));
    return r;
}
__device__ __forceinline__ float bflo(float v) {   // residual after bf16 round
    bf16 h = __float2bfloat16(v);
    return v - __bfloat162float(h);
}

// ---------------------------------------------------------------------------
// RoPE table
// ---------------------------------------------------------------------------
__global__ void rope_table_kernel() {
    int idx = blockIdx.x * blockDim.x + threadIdx.x;
    if (idx >= NTOK * 32) return;
    int t = idx / 32, dd = idx % 32;
    int y = t / 14, x = t % 14;
    float pos = (dd < 16) ? (float)y : (float)x;
    int j = (dd < 16) ? dd : dd - 16;
    float invf = exp2f(-(float)j * (log2f(10000.0f) / 16.0f));
    float ang = pos * invf;
    float s, c;
    sincosf(ang, &s, &c);
    g_cos[idx] = c;
    g_sin[idx] = s;
}

// ---------------------------------------------------------------------------
// fp32 -> bf16 (hi, lo) residual split
// ---------------------------------------------------------------------------
__global__ void split_kernel(const float4* __restrict__ src,
                             __nv_bfloat162* __restrict__ hi,
                             __nv_bfloat162* __restrict__ lo, int n4) {
    int i = blockIdx.x * blockDim.x + threadIdx.x;
    if (i >= n4) return;
    float4 v = src[i];
    bf16 h0 = __float2bfloat16(v.x), h1 = __float2bfloat16(v.y);
    bf16 h2 = __float2bfloat16(v.z), h3 = __float2bfloat16(v.w);
    bf16 l0 = __float2bfloat16(v.x - __bfloat162float(h0));
    bf16 l1 = __float2bfloat16(v.y - __bfloat162float(h1));
    bf16 l2 = __float2bfloat16(v.z - __bfloat162float(h2));
    bf16 l3 = __float2bfloat16(v.w - __bfloat162float(h3));
    hi[2 * i]     = __halves2bfloat162(h0, h1);
    hi[2 * i + 1] = __halves2bfloat162(h2, h3);
    lo[2 * i]     = __halves2bfloat162(l0, l1);
    lo[2 * i + 1] = __halves2bfloat162(l2, l3);
}

// ---------------------------------------------------------------------------
// mma.sync bf16 3-split GEMM (unchanged from passing R13)
// ---------------------------------------------------------------------------
#define ROWP 40   // bf16 elems per smem row (32 data + 8 pad), 80 B

__global__ __launch_bounds__(256)
void hmma_gemm_kernel(const bf16* __restrict__ Ahi, const bf16* __restrict__ Alo,
                      const bf16* __restrict__ Bhi, const bf16* __restrict__ Blo,
                      const float* __restrict__ bias, float* __restrict__ Cout,
                      int mode) {
    __shared__ bf16 sAh[128 * ROWP];
    __shared__ bf16 sAl[128 * ROWP];
    __shared__ bf16 sBh[128 * ROWP];
    __shared__ bf16 sBl[128 * ROWP];

    int tid = threadIdx.x, wid = tid >> 5, lane = tid & 31;
    int bn = blockIdx.x, bm = blockIdx.y;
    int wm = wid >> 1, wn = wid & 1;     // 4 x 2 warp grid

    float acc[2][8][4];
#pragma unroll
    for (int i = 0; i < 2; i++)
#pragma unroll
        for (int j = 0; j < 8; j++)
#pragma unroll
            for (int q = 0; q < 4; q++) acc[i][j][q] = 0.0f;

    int r0 = tid >> 2,          c80 = tid & 3;
    int r1 = (tid + 256) >> 2,  c81 = (tid + 256) & 3;

    const int NCH = KDIM / 32;   // 24
    for (int c = 0; c < NCH; c++) {
        size_t a0 = ((size_t)(bm * 128 + r0)) * KDIM + c * 32 + c80 * 8;
        size_t a1 = ((size_t)(bm * 128 + r1)) * KDIM + c * 32 + c81 * 8;
        size_t b0 = ((size_t)(bn * 128 + r0)) * KDIM + c * 32 + c80 * 8;
        size_t b1 = ((size_t)(bn * 128 + r1)) * KDIM + c * 32 + c81 * 8;
        uint4 tAh0 = *(const uint4*)&Ahi[a0];
        uint4 tAh1 = *(const uint4*)&Ahi[a1];
        uint4 tAl0 = *(const uint4*)&Alo[a0];
        uint4 tAl1 = *(const uint4*)&Alo[a1];
        uint4 tBh0 = *(const uint4*)&Bhi[b0];
        uint4 tBh1 = *(const uint4*)&Bhi[b1];
        uint4 tBl0 = *(const uint4*)&Blo[b0];
        uint4 tBl1 = *(const uint4*)&Blo[b1];
        __syncthreads();
        *(uint4*)&sAh[r0 * ROWP + c80 * 8] = tAh0;
        *(uint4*)&sAh[r1 * ROWP + c81 * 8] = tAh1;
        *(uint4*)&sAl[r0 * ROWP + c80 * 8] = tAl0;
        *(uint4*)&sAl[r1 * ROWP + c81 * 8] = tAl1;
        *(uint4*)&sBh[r0 * ROWP + c80 * 8] = tBh0;
        *(uint4*)&sBh[r1 * ROWP + c81 * 8] = tBh1;
        *(uint4*)&sBl[r0 * ROWP + c80 * 8] = tBl0;
        *(uint4*)&sBl[r1 * ROWP + c81 * 8] = tBl1;
        __syncthreads();

        int lr = lane & 7, sel = lane >> 3;
#pragma unroll
        for (int kk = 0; kk < 2; kk++) {
            uint32_t af[2][2][4];
#pragma unroll
            for (int mi = 0; mi < 2; mi++) {
                int m = wm * 32 + mi * 16 + (sel & 1) * 8 + lr;
                int k = kk * 16 + (sel >> 1) * 8;
                ldsm_x4(af[mi][0], smem_u32(&sAh[m * ROWP + k]));
                ldsm_x4(af[mi][1], smem_u32(&sAl[m * ROWP + k]));
            }
            uint32_t bfr[4][2][4];
#pragma unroll
            for (int np = 0; np < 4; np++) {
                int n = wn * 64 + np * 16 + (sel >> 1) * 8 + lr;
                int k = kk * 16 + (sel & 1) * 8;
                ldsm_x4(bfr[np][0], smem_u32(&sBh[n * ROWP + k]));
                ldsm_x4(bfr[np][1], smem_u32(&sBl[n * ROWP + k]));
            }
#pragma unroll
            for (int mi = 0; mi < 2; mi++)
#pragma unroll
                for (int nt = 0; nt < 8; nt++) {
                    const uint32_t* bh = &bfr[nt >> 1][0][(nt & 1) * 2];
                    const uint32_t* bl = &bfr[nt >> 1][1][(nt & 1) * 2];
                    mma16816(acc[mi][nt], af[mi][0], bh);
                    mma16816(acc[mi][nt], af[mi][0], bl);
                    mma16816(acc[mi][nt], af[mi][1], bh);
                }
        }
    }

    int nbase = bn * 128 + wn * 64;
    if (mode == 0) {
        int s = nbase / CDIM;
        int h = (nbase % CDIM) >> 6;
        float* dst = (s == 0) ? g_Q : (s == 1) ? g_K : g_V;
#pragma unroll
        for (int mi = 0; mi < 2; mi++)
#pragma unroll
            for (int rg = 0; rg < 2; rg++) {
                int m = bm * 128 + wm * 32 + mi * 16 + rg * 8 + (lane >> 2);
                int b = m / NTOK, t = m % NTOK;
                size_t off = (((size_t)(b * NHEADS + h)) * NTOK + t) * HD;
#pragma unroll
                for (int nt = 0; nt < 4; nt++)
#pragma unroll
                    for (int i = 0; i < 2; i++) {
                        int d = nt * 8 + 2 * (lane & 3) + i;
                        float lo = acc[mi][nt][rg * 2 + i]     + bias[nbase + d];
                        float hi = acc[mi][nt + 4][rg * 2 + i] + bias[nbase + d + 32];
                        if (s < 2) {
                            float cc = g_cos[t * 32 + d];
                            float sn = g_sin[t * 32 + d];
                            dst[off + d]      = lo * cc - hi * sn;
                            dst[off + d + 32] = hi * cc + lo * sn;
                        } else {
                            dst[off + d]      = lo;
                            dst[off + d + 32] = hi;
                        }
                    }
            }
    } else {
#pragma unroll
        for (int mi = 0; mi < 2; mi++)
#pragma unroll
            for (int rg = 0; rg < 2; rg++) {
                int m = bm * 128 + wm * 32 + mi * 16 + rg * 8 + (lane >> 2);
#pragma unroll
                for (int nt = 0; nt < 8; nt++) {
                    int n = nbase + nt * 8 + 2 * (lane & 3);
                    float2 w = make_float2(acc[mi][nt][rg * 2]     + bias[n],
                                           acc[mi][nt][rg * 2 + 1] + bias[n + 1]);
                    *(float2*)&Cout[(size_t)m * CDIM + n] = w;
                }
            }
    }
}

// ---------------------------------------------------------------------------
// Attention v3 (mma.sync): one block per (b,h), 8 warps.
// K, V^T split to bf16 hi/lo in smem; Q fragments from global, split in regs.
// Rows padded to 208 (13 m16 tiles); warp handles mt = warp, warp+8.
// S C-frags reused in place as P A-frags (flash-attn register trick).
// 3-split on both QK^T and PV.
// ---------------------------------------------------------------------------
#define KROWP 72        // K smem row: 64 + 8 pad bf16 (144 B)
#define VROWP 216       // Vt smem row: 208 + 8 pad bf16 (432 B)
#define KH_OFF 0
#define KL_OFF (208 * KROWP)
#define VH_OFF (2 * 208 * KROWP)
#define VL_OFF (VH_OFF + 64 * VROWP)
#define ATT2_ELEMS (VL_OFF + 64 * VROWP)          // bf16 elems
#define ATT2_SMEM  (ATT2_ELEMS * 2)               // 115,200 B

__global__ __launch_bounds__(256)
void attention_mma_kernel(float* __restrict__ AO) {
    extern __shared__ bf16 sm2[];
    bf16* sKh = sm2 + KH_OFF;
    bf16* sKl = sm2 + KL_OFF;
    bf16* sVh = sm2 + VH_OFF;
    bf16* sVl = sm2 + VL_OFF;

    int bh = blockIdx.x;
    int b = bh / NHEADS, h = bh % NHEADS;
    int tid = threadIdx.x, warp = tid >> 5, lane = tid & 31;

    const float* Qg = g_Q + (size_t)bh * NTOK * HD;
    const float* Kg = g_K + (size_t)bh * NTOK * HD;
    const float* Vg = g_V + (size_t)bh * NTOK * HD;

    // zero smem (covers padded rows/cols)
    for (int i = tid; i < ATT2_ELEMS / 2; i += 256)
        ((uint32_t*)sm2)[i] = 0u;
    __syncthreads();

    // load + split K and V^T
    for (int i = tid; i < NTOK * HD; i += 256) {
        int j = i >> 6, d = i & 63;
        float kv = Kg[i];
        bf16 kh = __float2bfloat16(kv);
        sKh[j * KROWP + d] = kh;
        sKl[j * KROWP + d] = __float2bfloat16(kv - __bfloat162float(kh));
        float vv = Vg[i];
        bf16 vh = __float2bfloat16(vv);
        sVh[d * VROWP + j] = vh;
        sVl[d * VROWP + j] = __float2bfloat16(vv - __bfloat162float(vh));
    }
    __syncthreads();

    const float scale = 0.125f;
    int lr = lane & 7, sel = lane >> 3;
    int qr = lane >> 2, qc = lane & 3;

    for (int mt = warp; mt < 13; mt += 8) {
        int mbase = mt * 16;
        int rA = mbase + qr;          // row for c0,c1
        int rB = rA + 8;              // row for c2,c3
        int rAc = (rA < NTOK) ? rA : NTOK - 1;
        int rBc = (rB < NTOK) ? rB : NTOK - 1;

        // ---- Q fragments from global, hi/lo split in registers ----
        uint32_t qh[4][4], ql[4][4];
#pragma unroll
        for (int kt = 0; kt < 4; kt++) {
            int k0 = kt * 16 + 2 * qc;
            float2 xA0 = *(const float2*)&Qg[rAc * HD + k0];
            float2 xB0 = *(const float2*)&Qg[rBc * HD + k0];
            float2 xA1 = *(const float2*)&Qg[rAc * HD + k0 + 8];
            float2 xB1 = *(const float2*)&Qg[rBc * HD + k0 + 8];
            qh[kt][0] = packbf(xA0.x, xA0.y);
            qh[kt][1] = packbf(xB0.x, xB0.y);
            qh[kt][2] = packbf(xA1.x, xA1.y);
            qh[kt][3] = packbf(xB1.x, xB1.y);
            ql[kt][0] = packbf(bflo(xA0.x), bflo(xA0.y));
            ql[kt][1] = packbf(bflo(xB0.x), bflo(xB0.y));
            ql[kt][2] = packbf(bflo(xA1.x), bflo(xA1.y));
            ql[kt][3] = packbf(bflo(xB1.x), bflo(xB1.y));
        }

        // ---- S = Q K^T : 26 n8-tile accumulators ----
        float sacc[26][4];
#pragma unroll
        for (int nt = 0; nt < 26; nt++)
#pragma unroll
            for (int q = 0; q < 4; q++) sacc[nt][q] = 0.0f;

#pragma unroll
        for (int kt = 0; kt < 4; kt++) {
#pragma unroll
            for (int ng = 0; ng < 13; ng++) {
                int n = ng * 16 + (sel >> 1) * 8 + lr;
                int k = kt * 16 + (sel & 1) * 8;
                uint32_t bfh[4], bfl[4];
                ldsm_x4(bfh, smem_u32(&sKh[n * KROWP + k]));
                ldsm_x4(bfl, smem_u32(&sKl[n * KROWP + k]));
#pragma unroll
                for (int sub = 0; sub < 2; sub++) {
                    mma16816(sacc[2 * ng + sub], qh[kt], &bfh[sub * 2]);
                    mma16816(sacc[2 * ng + sub], qh[kt], &bfl[sub * 2]);
                    mma16816(sacc[2 * ng + sub], ql[kt], &bfh[sub * 2]);
                }
            }
        }

        // ---- mask padded cols ----
#pragma unroll
        for (int nt = 24; nt < 26; nt++) {
            int jb = nt * 8 + 2 * qc;
            if (jb >= NTOK)     { sacc[nt][0] = -1e30f; sacc[nt][2] = -1e30f; }
            if (jb + 1 >= NTOK) { sacc[nt][1] = -1e30f; sacc[nt][3] = -1e30f; }
        }

        // ---- softmax (rows rA, rB) ----
        float mA = -1e30f, mB = -1e30f;
#pragma unroll
        for (int nt = 0; nt < 26; nt++) {
            mA = fmaxf(mA, fmaxf(sacc[nt][0], sacc[nt][1]));
            mB = fmaxf(mB, fmaxf(sacc[nt][2], sacc[nt][3]));
        }
        mA = fmaxf(mA, __shfl_xor_sync(0xFFFFFFFFu, mA, 1));
        mA = fmaxf(mA, __shfl_xor_sync(0xFFFFFFFFu, mA, 2));
        mB = fmaxf(mB, __shfl_xor_sync(0xFFFFFFFFu, mB, 1));
        mB = fmaxf(mB, __shfl_xor_sync(0xFFFFFFFFu, mB, 2));
        float mscA = mA * scale, mscB = mB * scale;

        float zA = 0.0f, zB = 0.0f;
#pragma unroll
        for (int nt = 0; nt < 26; nt++) {
            sacc[nt][0] = __expf(fmaf(sacc[nt][0], scale, -mscA));
            sacc[nt][1] = __expf(fmaf(sacc[nt][1], scale, -mscA));
            sacc[nt][2] = __expf(fmaf(sacc[nt][2], scale, -mscB));
            sacc[nt][3] = __expf(fmaf(sacc[nt][3], scale, -mscB));
            zA += sacc[nt][0] + sacc[nt][1];
            zB += sacc[nt][2] + sacc[nt][3];
        }
        zA += __shfl_xor_sync(0xFFFFFFFFu, zA, 1);
        zA += __shfl_xor_sync(0xFFFFFFFFu, zA, 2);
        zB += __shfl_xor_sync(0xFFFFFFFFu, zB, 1);
        zB += __shfl_xor_sync(0xFFFFFFFFu, zB, 2);
        float invA = 1.0f / zA, invB = 1.0f / zB;

        // ---- O = P V : P frags built from sacc in place ----
        float oacc[8][4];
#pragma unroll
        for (int dt = 0; dt < 8; dt++)
#pragma unroll
            for (int q = 0; q < 4; q++) oacc[dt][q] = 0.0f;

#pragma unroll
        for (int jt = 0; jt < 13; jt++) {
            uint32_t ph[4], pl[4];
            {
                const float* p0 = sacc[2 * jt];
                const float* p1 = sacc[2 * jt + 1];
                ph[0] = packbf(p0[0], p0[1]);
                ph[1] = packbf(p0[2], p0[3]);
                ph[2] = packbf(p1[0], p1[1]);
                ph[3] = packbf(p1[2], p1[3]);
                pl[0] = packbf(bflo(p0[0]), bflo(p0[1]));
                pl[1] = packbf(bflo(p0[2]), bflo(p0[3]));
                pl[2] = packbf(bflo(p1[0]), bflo(p1[1]));
                pl[3] = packbf(bflo(p1[2]), bflo(p1[3]));
            }
#pragma unroll
            for (int dg = 0; dg < 4; dg++) {
                int n = dg * 16 + (sel >> 1) * 8 + lr;
                int k = jt * 16 + (sel & 1) * 8;
                uint32_t bfh[4], bfl[4];
                ldsm_x4(bfh, smem_u32(&sVh[n * VROWP + k]));
                ldsm_x4(bfl, smem_u32(&sVl[n * VROWP + k]));
#pragma unroll
                for (int sub = 0; sub < 2; sub++) {
                    mma16816(oacc[2 * dg + sub], ph, &bfh[sub * 2]);
                    mma16816(oacc[2 * dg + sub], ph, &bfl[sub * 2]);
                    mma16816(oacc[2 * dg + sub], pl, &bfh[sub * 2]);
                }
            }
        }

        // ---- write normalized output ----
        if (rA < NTOK) {
            size_t base = ((size_t)b * NTOK + rA) * CDIM + h * HD;
#pragma unroll
            for (int dt = 0; dt < 8; dt++) {
                int d = dt * 8 + 2 * qc;
                *(float2*)&AO[base + d] =
                    make_float2(oacc[dt][0] * invA, oacc[dt][1] * invA);
            }
        }
        if (rB < NTOK) {
            size_t base = ((size_t)b * NTOK + rB) * CDIM + h * HD;
#pragma unroll
            for (int dt = 0; dt < 8; dt++) {
                int d = dt * 8 + 2 * qc;
                *(float2*)&AO[base + d] =
                    make_float2(oacc[dt][2] * invB, oacc[dt][3] * invB);
            }
        }
    }
}

// ---------------------------------------------------------------------------
extern "C" void kernel_launch(void* const* d_in, const int* in_sizes, int n_in,
                              void* d_out, int out_size) {
    const float* x      = (const float*)d_in[0];
    const float* qkv_w  = (const float*)d_in[1];
    const float* qkv_b  = (const float*)d_in[2];
    const float* proj_w = (const float*)d_in[3];
    const float* proj_b = (const float*)d_in[4];
    float* out = (float*)d_out;

    bf16 *xh, *xl, *wh, *wl, *ph, *pl, *aoh, *aol;
    float *aop;
    cudaGetSymbolAddress((void**)&xh, g_xh);   cudaGetSymbolAddress((void**)&xl, g_xl);
    cudaGetSymbolAddress((void**)&wh, g_wh);   cudaGetSymbolAddress((void**)&wl, g_wl);
    cudaGetSymbolAddress((void**)&ph, g_ph);   cudaGetSymbolAddress((void**)&pl, g_pl);
    cudaGetSymbolAddress((void**)&aoh, g_aoh); cudaGetSymbolAddress((void**)&aol, g_aol);
    cudaGetSymbolAddress((void**)&aop, g_AO);

    // 1. RoPE tables
    rope_table_kernel<<<(NTOK * 32 + 255) / 256, 256>>>();

    // 2. bf16 splits of x, qkv_w, proj_w
    {
        int n4 = MROWS * CDIM / 4;
        split_kernel<<<(n4 + 255) / 256, 256>>>((const float4*)x,
            (__nv_bfloat162*)xh, (__nv_bfloat162*)xl, n4);
        n4 = NQKV * CDIM / 4;
        split_kernel<<<(n4 + 255) / 256, 256>>>((const float4*)qkv_w,
            (__nv_bfloat162*)wh, (__nv_bfloat162*)wl, n4);
        n4 = CDIM * CDIM / 4;
        split_kernel<<<(n4 + 255) / 256, 256>>>((const float4*)proj_w,
            (__nv_bfloat162*)ph, (__nv_bfloat162*)pl, n4);
    }

    // 3. QKV GEMM (mma.sync) + fused RoPE + scatter
    {
        dim3 grid(NQKV / 128, MROWS / 128);   // (18, 196)
        hmma_gemm_kernel<<<grid, 256>>>(xh, xl, wh, wl, qkv_b, nullptr, 0);
    }

    // 4. Attention (mma.sync)
    {
        cudaFuncSetAttribute(attention_mma_kernel,
                             cudaFuncAttributeMaxDynamicSharedMemorySize,
                             ATT2_SMEM);
        attention_mma_kernel<<<BHTOT, 256, ATT2_SMEM>>>(aop);
    }

    // 5. split AO -> bf16
    {
        int n4 = MROWS * CDIM / 4;
        split_kernel<<<(n4 + 255) / 256, 256>>>((const float4*)aop,
            (__nv_bfloat162*)aoh, (__nv_bfloat162*)aol, n4);
    }

    // 6. Output projection (mma.sync)
    {
        dim3 grid(CDIM / 128, MROWS / 128);   // (6, 196)
        hmma_gemm_kernel<<<grid, 256>>>(aoh, aol, ph, pl, proj_b, out, 1);
    }
}